// round 1
// baseline (speedup 1.0000x reference)
#include <cuda_runtime.h>
#include <cuda_bf16.h>

#define Bb 32
#define Nn 4096
#define Mm 512
#define Cc 256

// Scratch (no allocations allowed in kernel_launch)
__device__ float d_cosT[Mm * Nn];           // cos(2*pi*m*n/N), [m][n]
__device__ float d_sinT[Mm * Nn];           // sin(2*pi*m*n/N), [m][n]
__device__ float d_Fre[Bb * Mm * Cc];
__device__ float d_Fim[Bb * Mm * Cc];
__device__ float d_Gre[Bb * Mm * Cc];       // includes w_m/N scale
__device__ float d_Gim[Bb * Mm * Cc];

// ---------------------------------------------------------------------------
// Twiddle tables. Argument 2*t/N with t = (m*n mod N) is exactly representable
// (N power of two), so sincospif is near-exact.
// ---------------------------------------------------------------------------
__global__ void twiddle_kernel() {
    int idx = blockIdx.x * blockDim.x + threadIdx.x;
    if (idx >= Mm * Nn) return;
    int m = idx / Nn;
    int n = idx - m * Nn;
    int t = (int)(((long long)m * (long long)n) & (Nn - 1));
    float x = 2.0f * (float)t / (float)Nn;
    float s, c;
    sincospif(x, &s, &c);
    d_cosT[idx] = c;
    d_sinT[idx] = s;
}

// ---------------------------------------------------------------------------
// Forward: F_re[b,m,i] = sum_n cos[m,n] * v[b,n,i]
//          F_im[b,m,i] = -sum_n sin[m,n] * v[b,n,i]
// Tiled GEMM, BM=BN=64, BK=16, 256 threads, 4x4 per thread, two accumulator
// sets sharing the v tile.
// grid: (Cc/64, Mm/64, Bb)
// ---------------------------------------------------------------------------
__global__ __launch_bounds__(256) void forward_kernel(const float* __restrict__ v) {
    __shared__ float Asc[16][68];   // [k][m_row], padded, 16B-aligned rows
    __shared__ float Ass[16][68];
    __shared__ float Bs[16][64];    // [k][i_col]

    const int b  = blockIdx.z;
    const int m0 = blockIdx.y * 64;
    const int i0 = blockIdx.x * 64;
    const int tid = threadIdx.x;
    const int tx = tid & 15;
    const int ty = tid >> 4;

    float acc_re[4][4] = {};
    float acc_im[4][4] = {};

    const float* vb = v + (size_t)b * Nn * Cc;

    const int la_c  = tid & 15;   // k within tile
    const int la_r0 = tid >> 4;   // m row base
    const int lb_c  = tid & 63;   // i col
    const int lb_r0 = tid >> 6;   // k row base

    for (int k0 = 0; k0 < Nn; k0 += 16) {
        #pragma unroll
        for (int i = 0; i < 4; i++) {
            int r = la_r0 + i * 16;
            size_t g = (size_t)(m0 + r) * Nn + (size_t)(k0 + la_c);
            Asc[la_c][r] = d_cosT[g];
            Ass[la_c][r] = d_sinT[g];
        }
        #pragma unroll
        for (int i = 0; i < 4; i++) {
            int r = lb_r0 + i * 4;
            Bs[r][lb_c] = vb[(size_t)(k0 + r) * Cc + (size_t)(i0 + lb_c)];
        }
        __syncthreads();

        #pragma unroll
        for (int k = 0; k < 16; k++) {
            float4 ac4 = *(const float4*)&Asc[k][ty * 4];
            float4 as4 = *(const float4*)&Ass[k][ty * 4];
            float4 bv4 = *(const float4*)&Bs[k][tx * 4];
            float ac[4] = {ac4.x, ac4.y, ac4.z, ac4.w};
            float as_[4] = {as4.x, as4.y, as4.z, as4.w};
            float bv[4] = {bv4.x, bv4.y, bv4.z, bv4.w};
            #pragma unroll
            for (int i = 0; i < 4; i++)
                #pragma unroll
                for (int j = 0; j < 4; j++) {
                    acc_re[i][j] += ac[i]  * bv[j];
                    acc_im[i][j] += as_[i] * bv[j];
                }
        }
        __syncthreads();
    }

    #pragma unroll
    for (int i = 0; i < 4; i++) {
        int m = m0 + ty * 4 + i;
        size_t base = (size_t)b * Mm * Cc + (size_t)m * Cc + (size_t)(i0 + tx * 4);
        float4 re = make_float4(acc_re[i][0], acc_re[i][1], acc_re[i][2], acc_re[i][3]);
        float4 im = make_float4(-acc_im[i][0], -acc_im[i][1], -acc_im[i][2], -acc_im[i][3]);
        *(float4*)&d_Fre[base] = re;
        *(float4*)&d_Fim[base] = im;
    }
}

// ---------------------------------------------------------------------------
// Mid: G'[b,m,o] = (w_m/N) * sum_i R[m,i,o] * F[b,m,i]   (re and im)
// Per block: one mode m, one 64-wide o-tile, all 32 batches.
// BM=32 (b), BN=64 (o), K=256 (i) in chunks of 16. 256 threads, 2x4 x2 acc.
// grid: (Cc/64, Mm)
// ---------------------------------------------------------------------------
__global__ __launch_bounds__(256) void mid_kernel(const float* __restrict__ R) {
    __shared__ float Are[16][34];   // [k][b]
    __shared__ float Aim[16][34];
    __shared__ float Bs[16][64];    // [k][o]

    const int m  = blockIdx.y;
    const int o0 = blockIdx.x * 64;
    const int tid = threadIdx.x;
    const int tx = tid & 15;
    const int ty = tid >> 4;

    float ar[2][4] = {};
    float ai[2][4] = {};

    const float* Rm = R + (size_t)m * Cc * Cc;

    const int la_c  = tid & 15;  // k
    const int la_r0 = tid >> 4;  // b base
    const int lb_c  = tid & 63;
    const int lb_r0 = tid >> 6;

    for (int k0 = 0; k0 < Cc; k0 += 16) {
        #pragma unroll
        for (int i = 0; i < 2; i++) {
            int r = la_r0 + i * 16;  // b
            size_t g = (size_t)r * Mm * Cc + (size_t)m * Cc + (size_t)(k0 + la_c);
            Are[la_c][r] = d_Fre[g];
            Aim[la_c][r] = d_Fim[g];
        }
        #pragma unroll
        for (int i = 0; i < 4; i++) {
            int r = lb_r0 + i * 4;
            Bs[r][lb_c] = Rm[(size_t)(k0 + r) * Cc + (size_t)(o0 + lb_c)];
        }
        __syncthreads();

        #pragma unroll
        for (int k = 0; k < 16; k++) {
            float are0 = Are[k][ty * 2];
            float are1 = Are[k][ty * 2 + 1];
            float aim0 = Aim[k][ty * 2];
            float aim1 = Aim[k][ty * 2 + 1];
            float4 bv4 = *(const float4*)&Bs[k][tx * 4];
            float bv[4] = {bv4.x, bv4.y, bv4.z, bv4.w};
            #pragma unroll
            for (int j = 0; j < 4; j++) {
                ar[0][j] += are0 * bv[j];
                ar[1][j] += are1 * bv[j];
                ai[0][j] += aim0 * bv[j];
                ai[1][j] += aim1 * bv[j];
            }
        }
        __syncthreads();
    }

    const float scale = (m == 0) ? (1.0f / (float)Nn) : (2.0f / (float)Nn);

    #pragma unroll
    for (int i = 0; i < 2; i++) {
        int bidx = ty * 2 + i;
        size_t base = (size_t)bidx * Mm * Cc + (size_t)m * Cc + (size_t)(o0 + tx * 4);
        float4 re = make_float4(scale * ar[i][0], scale * ar[i][1],
                                scale * ar[i][2], scale * ar[i][3]);
        float4 im = make_float4(scale * ai[i][0], scale * ai[i][1],
                                scale * ai[i][2], scale * ai[i][3]);
        *(float4*)&d_Gre[base] = re;
        *(float4*)&d_Gim[base] = im;
    }
}

// ---------------------------------------------------------------------------
// Inverse: out[b,n,o] = v[b,n,o] + sum_m (cos[m,n]*G_re[b,m,o] - sin[m,n]*G_im[b,m,o])
// BM=64 (n), BN=64 (o), K=512 (m) in chunks of 16.
// grid: (Cc/64, Nn/64, Bb)
// ---------------------------------------------------------------------------
__global__ __launch_bounds__(256) void inverse_kernel(const float* __restrict__ v,
                                                      float* __restrict__ out) {
    __shared__ float Asc[16][68];   // [k=m][n]
    __shared__ float Ass[16][68];
    __shared__ float Bre[16][64];   // [k=m][o]
    __shared__ float Bim[16][64];

    const int b  = blockIdx.z;
    const int n0 = blockIdx.y * 64;
    const int o0 = blockIdx.x * 64;
    const int tid = threadIdx.x;
    const int tx = tid & 15;
    const int ty = tid >> 4;

    float acc[4][4] = {};

    const size_t gbase = (size_t)b * Mm * Cc;

    const int la_c  = tid & 63;   // n col
    const int la_r0 = tid >> 6;   // k row base
    const int lb_c  = tid & 63;   // o col
    const int lb_r0 = tid >> 6;   // k row base

    for (int k0 = 0; k0 < Mm; k0 += 16) {
        #pragma unroll
        for (int i = 0; i < 4; i++) {
            int kk = la_r0 + i * 4;
            size_t g = (size_t)(k0 + kk) * Nn + (size_t)(n0 + la_c);
            Asc[kk][la_c] = d_cosT[g];
            Ass[kk][la_c] = d_sinT[g];
        }
        #pragma unroll
        for (int i = 0; i < 4; i++) {
            int kk = lb_r0 + i * 4;
            size_t g = gbase + (size_t)(k0 + kk) * Cc + (size_t)(o0 + lb_c);
            Bre[kk][lb_c] = d_Gre[g];
            Bim[kk][lb_c] = d_Gim[g];
        }
        __syncthreads();

        #pragma unroll
        for (int k = 0; k < 16; k++) {
            float4 ac4 = *(const float4*)&Asc[k][ty * 4];
            float4 as4 = *(const float4*)&Ass[k][ty * 4];
            float4 br4 = *(const float4*)&Bre[k][tx * 4];
            float4 bi4 = *(const float4*)&Bim[k][tx * 4];
            float ac[4] = {ac4.x, ac4.y, ac4.z, ac4.w};
            float as_[4] = {as4.x, as4.y, as4.z, as4.w};
            float br[4] = {br4.x, br4.y, br4.z, br4.w};
            float bi[4] = {bi4.x, bi4.y, bi4.z, bi4.w};
            #pragma unroll
            for (int i = 0; i < 4; i++)
                #pragma unroll
                for (int j = 0; j < 4; j++) {
                    acc[i][j] += ac[i] * br[j];
                    acc[i][j] -= as_[i] * bi[j];
                }
        }
        __syncthreads();
    }

    #pragma unroll
    for (int i = 0; i < 4; i++) {
        int n = n0 + ty * 4 + i;
        size_t base = ((size_t)b * Nn + (size_t)n) * Cc + (size_t)(o0 + tx * 4);
        float4 vv = *(const float4*)&v[base];
        float4 r = make_float4(vv.x + acc[i][0], vv.y + acc[i][1],
                               vv.z + acc[i][2], vv.w + acc[i][3]);
        *(float4*)&out[base] = r;
    }
}

extern "C" void kernel_launch(void* const* d_in, const int* in_sizes, int n_in,
                              void* d_out, int out_size) {
    const float* v = (const float*)d_in[0];
    const float* R = (const float*)d_in[1];
    float* out = (float*)d_out;

    twiddle_kernel<<<(Mm * Nn + 255) / 256, 256>>>();
    forward_kernel<<<dim3(Cc / 64, Mm / 64, Bb), 256>>>(v);
    mid_kernel<<<dim3(Cc / 64, Mm), 256>>>(R);
    inverse_kernel<<<dim3(Cc / 64, Nn / 64, Bb), 256>>>(v, out);
}

// round 3
// speedup vs baseline: 1.8336x; 1.8336x over previous
#include <cuda_runtime.h>
#include <cuda_bf16.h>
#include <mma.h>
#include <cstdint>

using namespace nvcuda;

#define Bb 32
#define Nn 4096
#define Mm 512
#define Cc 256

// ---------------------------------------------------------------------------
// Global scratch (static __device__ — no runtime allocation)
// ---------------------------------------------------------------------------
__device__ __align__(16) __nv_bfloat16 g_Ach[Mm * Nn];
__device__ __align__(16) __nv_bfloat16 g_Acl[Mm * Nn];
__device__ __align__(16) __nv_bfloat16 g_Ash[Mm * Nn];   // holds -sin hi
__device__ __align__(16) __nv_bfloat16 g_Asl[Mm * Nn];   // holds -sin lo
__device__ __align__(16) __nv_bfloat16 g_AinvH[Nn * 2 * Mm];
__device__ __align__(16) __nv_bfloat16 g_AinvL[Nn * 2 * Mm];
__device__ __align__(16) __nv_bfloat16 g_Vh[(size_t)Bb * Nn * Cc];
__device__ __align__(16) __nv_bfloat16 g_Vl[(size_t)Bb * Nn * Cc];
__device__ __align__(16) __nv_bfloat16 g_Gh[(size_t)Bb * 2 * Mm * Cc];
__device__ __align__(16) __nv_bfloat16 g_Gl[(size_t)Bb * 2 * Mm * Cc];
__device__ float d_Fre[Bb * Mm * Cc];
__device__ float d_Fim[Bb * Mm * Cc];
__device__ float d_Gre[Bb * Mm * Cc];
__device__ float d_Gim[Bb * Mm * Cc];

// ---------------------------------------------------------------------------
__device__ __forceinline__ uint32_t s2u(const void* p) {
    uint32_t a;
    asm("{ .reg .u64 t; cvta.to.shared.u64 t, %1; cvt.u32.u64 %0, t; }"
        : "=r"(a) : "l"(p));
    return a;
}

#define CP16(dst, src) \
    asm volatile("cp.async.cg.shared.global [%0], [%1], 16;" :: "r"(dst), "l"(src))
#define CP_COMMIT() asm volatile("cp.async.commit_group;")
#define CP_WAIT1()  asm volatile("cp.async.wait_group 1;" ::: "memory")
#define CP_WAIT0()  asm volatile("cp.async.wait_group 0;" ::: "memory")

__device__ __forceinline__ void split_bf16(float x, __nv_bfloat16& hi, __nv_bfloat16& lo) {
    hi = __float2bfloat16(x);
    lo = __float2bfloat16(x - __bfloat162float(hi));
}

typedef wmma::fragment<wmma::matrix_a, 16, 16, 16, __nv_bfloat16, wmma::row_major> FragA;
typedef wmma::fragment<wmma::matrix_b, 16, 16, 16, __nv_bfloat16, wmma::row_major> FragB;
typedef wmma::fragment<wmma::accumulator, 16, 16, 16, float> FragC;

// ---------------------------------------------------------------------------
// Prep kernels
// ---------------------------------------------------------------------------
__global__ __launch_bounds__(256) void genA_fwd() {
    int idx = blockIdx.x * blockDim.x + threadIdx.x;
    if (idx >= Mm * Nn) return;
    int m = idx >> 12, n = idx & (Nn - 1);
    int t = (int)(((long long)m * n) & (Nn - 1));
    float s, c;
    sincospif((float)t * (1.0f / 2048.0f), &s, &c);
    __nv_bfloat16 h, l;
    split_bf16(c, h, l);
    g_Ach[idx] = h; g_Acl[idx] = l;
    split_bf16(-s, h, l);
    g_Ash[idx] = h; g_Asl[idx] = l;
}

__global__ __launch_bounds__(256) void genA_inv() {
    int idx = blockIdx.x * blockDim.x + threadIdx.x;
    if (idx >= Nn * 2 * Mm) return;
    int n = idx >> 10, mp = idx & 1023;
    int m = (mp < Mm) ? mp : (mp - Mm);
    int t = (int)(((long long)m * n) & (Nn - 1));
    float s, c;
    sincospif((float)t * (1.0f / 2048.0f), &s, &c);
    float val = (mp < Mm) ? c : s;
    __nv_bfloat16 h, l;
    split_bf16(val, h, l);
    g_AinvH[idx] = h; g_AinvL[idx] = l;
}

__global__ __launch_bounds__(256) void packV(const float* __restrict__ v) {
    size_t i4 = (size_t)blockIdx.x * blockDim.x + threadIdx.x;
    size_t base = i4 * 4;
    if (base >= (size_t)Bb * Nn * Cc) return;
    float4 x = *(const float4*)(v + base);
    __nv_bfloat16 h0, l0, h1, l1, h2, l2, h3, l3;
    split_bf16(x.x, h0, l0); split_bf16(x.y, h1, l1);
    split_bf16(x.z, h2, l2); split_bf16(x.w, h3, l3);
    *(__nv_bfloat162*)(g_Vh + base)     = __nv_bfloat162{h0, h1};
    *(__nv_bfloat162*)(g_Vh + base + 2) = __nv_bfloat162{h2, h3};
    *(__nv_bfloat162*)(g_Vl + base)     = __nv_bfloat162{l0, l1};
    *(__nv_bfloat162*)(g_Vl + base + 2) = __nv_bfloat162{l2, l3};
}

__global__ __launch_bounds__(256) void pack_G() {
    size_t i4 = (size_t)blockIdx.x * blockDim.x + threadIdx.x;
    size_t base = i4 * 4;
    if (base >= (size_t)Bb * 2 * Mm * Cc) return;
    int b = (int)(base >> 18);
    int rem = (int)(base & 262143);
    int mp = rem >> 8, o = rem & 255;
    float4 x;
    if (mp < Mm) {
        x = *(const float4*)(d_Gre + ((size_t)b * Mm + mp) * Cc + o);
    } else {
        float4 gi = *(const float4*)(d_Gim + ((size_t)b * Mm + (mp - Mm)) * Cc + o);
        x = make_float4(-gi.x, -gi.y, -gi.z, -gi.w);
    }
    __nv_bfloat16 h0, l0, h1, l1, h2, l2, h3, l3;
    split_bf16(x.x, h0, l0); split_bf16(x.y, h1, l1);
    split_bf16(x.z, h2, l2); split_bf16(x.w, h3, l3);
    *(__nv_bfloat162*)(g_Gh + base)     = __nv_bfloat162{h0, h1};
    *(__nv_bfloat162*)(g_Gh + base + 2) = __nv_bfloat162{h2, h3};
    *(__nv_bfloat162*)(g_Gl + base)     = __nv_bfloat162{l0, l1};
    *(__nv_bfloat162*)(g_Gl + base + 2) = __nv_bfloat162{l2, l3};
}

// ---------------------------------------------------------------------------
// Forward WMMA GEMM. CTA 128(m) x 128(i), 512 threads (16 warps, 4x4 of 32x32),
// K=4096 in 32-wide double-buffered cp.async chunks.
// ---------------------------------------------------------------------------
#define STAGE_FWD 58368

__device__ __forceinline__ void fwd_load(uint32_t sbase, int m0, int i0, int b,
                                         int k0, int tid) {
    int r = tid >> 2, s4 = tid & 3;
    size_t aoff = (size_t)(m0 + r) * Nn + k0 + s4 * 8;
    uint32_t ad = sbase + r * 80 + s4 * 16;
    CP16(ad,         g_Ach + aoff);
    CP16(ad + 10240, g_Acl + aoff);
    CP16(ad + 20480, g_Ash + aoff);
    CP16(ad + 30720, g_Asl + aoff);
    int kr = tid >> 4, s16 = tid & 15;
    size_t boff = ((size_t)b * Nn + k0 + kr) * Cc + i0 + s16 * 8;
    uint32_t bd = sbase + 40960 + kr * 272 + s16 * 16;
    CP16(bd,        g_Vh + boff);
    CP16(bd + 8704, g_Vl + boff);
    CP_COMMIT();
}

__global__ __launch_bounds__(512) void fwd_gemm() {
    extern __shared__ __align__(16) char sm[];
    const uint32_t sb = s2u(sm);
    const int tid = threadIdx.x;
    const int warpId = tid >> 5;
    const int wm = warpId >> 2, wi = warpId & 3;
    const int it = blockIdx.x, mt = blockIdx.y, b = blockIdx.z;
    const int m0 = mt * 128, i0 = it * 128;

    FragC accR[2][2], accI[2][2];
    #pragma unroll
    for (int a = 0; a < 2; a++)
        #pragma unroll
        for (int c = 0; c < 2; c++) {
            wmma::fill_fragment(accR[a][c], 0.0f);
            wmma::fill_fragment(accI[a][c], 0.0f);
        }

    fwd_load(sb, m0, i0, b, 0, tid);

    const int NCH = Nn / 32;
    for (int c = 0; c < NCH; c++) {
        int buf = c & 1;
        if (c + 1 < NCH) {
            fwd_load(sb + (buf ^ 1) * STAGE_FWD, m0, i0, b, (c + 1) * 32, tid);
            CP_WAIT1();
        } else {
            CP_WAIT0();
        }
        __syncthreads();

        const char* base = sm + buf * STAGE_FWD;
        const __nv_bfloat16* Ach = (const __nv_bfloat16*)(base);
        const __nv_bfloat16* Acl = (const __nv_bfloat16*)(base + 10240);
        const __nv_bfloat16* Ash = (const __nv_bfloat16*)(base + 20480);
        const __nv_bfloat16* Asl = (const __nv_bfloat16*)(base + 30720);
        const __nv_bfloat16* Bvh = (const __nv_bfloat16*)(base + 40960);
        const __nv_bfloat16* Bvl = (const __nv_bfloat16*)(base + 49664);

        #pragma unroll
        for (int ks = 0; ks < 2; ks++) {
            const int kk = ks * 16;
            FragB vh[2], vl[2];
            #pragma unroll
            for (int is_ = 0; is_ < 2; is_++) {
                wmma::load_matrix_sync(vh[is_], Bvh + kk * 136 + wi * 32 + is_ * 16, 136);
                wmma::load_matrix_sync(vl[is_], Bvl + kk * 136 + wi * 32 + is_ * 16, 136);
            }
            #pragma unroll
            for (int ms = 0; ms < 2; ms++) {
                const int ao = (wm * 32 + ms * 16) * 40 + kk;
                FragA ach, acl, ash, asl;
                wmma::load_matrix_sync(ach, Ach + ao, 40);
                wmma::load_matrix_sync(acl, Acl + ao, 40);
                wmma::load_matrix_sync(ash, Ash + ao, 40);
                wmma::load_matrix_sync(asl, Asl + ao, 40);
                #pragma unroll
                for (int is_ = 0; is_ < 2; is_++) {
                    wmma::mma_sync(accR[ms][is_], ach, vh[is_], accR[ms][is_]);
                    wmma::mma_sync(accR[ms][is_], ach, vl[is_], accR[ms][is_]);
                    wmma::mma_sync(accR[ms][is_], acl, vh[is_], accR[ms][is_]);
                    wmma::mma_sync(accI[ms][is_], ash, vh[is_], accI[ms][is_]);
                    wmma::mma_sync(accI[ms][is_], ash, vl[is_], accI[ms][is_]);
                    wmma::mma_sync(accI[ms][is_], asl, vh[is_], accI[ms][is_]);
                }
            }
        }
        __syncthreads();
    }

    #pragma unroll
    for (int ms = 0; ms < 2; ms++)
        #pragma unroll
        for (int is_ = 0; is_ < 2; is_++) {
            size_t off = ((size_t)b * Mm + m0 + wm * 32 + ms * 16) * Cc
                         + i0 + wi * 32 + is_ * 16;
            wmma::store_matrix_sync(d_Fre + off, accR[ms][is_], Cc, wmma::mem_row_major);
            wmma::store_matrix_sync(d_Fim + off, accI[ms][is_], Cc, wmma::mem_row_major);
        }
}

// ---------------------------------------------------------------------------
// Mid (fp32): G[b,m,o] = (w_m/N) * sum_i R[m,i,o] * F[b,m,i]
// ---------------------------------------------------------------------------
__global__ __launch_bounds__(256) void mid_kernel(const float* __restrict__ R) {
    __shared__ float Are[16][34];
    __shared__ float Aim[16][34];
    __shared__ float Bs[16][64];

    const int m = blockIdx.y;
    const int o0 = blockIdx.x * 64;
    const int tid = threadIdx.x;
    const int tx = tid & 15, ty = tid >> 4;

    float ar[2][4] = {}, ai[2][4] = {};
    const float* Rm = R + (size_t)m * Cc * Cc;
    const int la_c = tid & 15, la_r0 = tid >> 4;
    const int lb_c = tid & 63, lb_r0 = tid >> 6;

    for (int k0 = 0; k0 < Cc; k0 += 16) {
        #pragma unroll
        for (int i = 0; i < 2; i++) {
            int r = la_r0 + i * 16;
            size_t g = (size_t)r * Mm * Cc + (size_t)m * Cc + (k0 + la_c);
            Are[la_c][r] = d_Fre[g];
            Aim[la_c][r] = d_Fim[g];
        }
        #pragma unroll
        for (int i = 0; i < 4; i++) {
            int r = lb_r0 + i * 4;
            Bs[r][lb_c] = Rm[(size_t)(k0 + r) * Cc + o0 + lb_c];
        }
        __syncthreads();
        #pragma unroll
        for (int k = 0; k < 16; k++) {
            float are0 = Are[k][ty * 2], are1 = Are[k][ty * 2 + 1];
            float aim0 = Aim[k][ty * 2], aim1 = Aim[k][ty * 2 + 1];
            float4 b4 = *(const float4*)&Bs[k][tx * 4];
            float bv[4] = {b4.x, b4.y, b4.z, b4.w};
            #pragma unroll
            for (int j = 0; j < 4; j++) {
                ar[0][j] += are0 * bv[j];
                ar[1][j] += are1 * bv[j];
                ai[0][j] += aim0 * bv[j];
                ai[1][j] += aim1 * bv[j];
            }
        }
        __syncthreads();
    }
    const float scale = (m == 0) ? (1.0f / Nn) : (2.0f / Nn);
    #pragma unroll
    for (int i = 0; i < 2; i++) {
        int bidx = ty * 2 + i;
        size_t base = (size_t)bidx * Mm * Cc + (size_t)m * Cc + o0 + tx * 4;
        float4 re = make_float4(scale * ar[i][0], scale * ar[i][1], scale * ar[i][2], scale * ar[i][3]);
        float4 im = make_float4(scale * ai[i][0], scale * ai[i][1], scale * ai[i][2], scale * ai[i][3]);
        *(float4*)&d_Gre[base] = re;
        *(float4*)&d_Gim[base] = im;
    }
}

// ---------------------------------------------------------------------------
// Inverse WMMA GEMM. CTA 128(n) x 128(o), K = 1024 (cos|sin concat).
// ---------------------------------------------------------------------------
#define STAGE_INV 37888

__device__ __forceinline__ void inv_load(uint32_t sbase, int n0, int o0, int b,
                                         int k0, int tid) {
    int r = tid >> 2, s4 = tid & 3;
    size_t aoff = (size_t)(n0 + r) * 1024 + k0 + s4 * 8;
    uint32_t ad = sbase + r * 80 + s4 * 16;
    CP16(ad,         g_AinvH + aoff);
    CP16(ad + 10240, g_AinvL + aoff);
    int kr = tid >> 4, s16 = tid & 15;
    size_t boff = ((size_t)b * 1024 + k0 + kr) * Cc + o0 + s16 * 8;
    uint32_t bd = sbase + 20480 + kr * 272 + s16 * 16;
    CP16(bd,        g_Gh + boff);
    CP16(bd + 8704, g_Gl + boff);
    CP_COMMIT();
}

__global__ __launch_bounds__(512) void inv_gemm(const float* __restrict__ v,
                                                float* __restrict__ out) {
    extern __shared__ __align__(16) char sm[];
    const uint32_t sb = s2u(sm);
    const int tid = threadIdx.x;
    const int warpId = tid >> 5;
    const int wm = warpId >> 2, wi = warpId & 3;
    const int ot = blockIdx.x, nt = blockIdx.y, b = blockIdx.z;
    const int n0 = nt * 128, o0 = ot * 128;

    FragC acc[2][2];
    #pragma unroll
    for (int a = 0; a < 2; a++)
        #pragma unroll
        for (int c = 0; c < 2; c++) wmma::fill_fragment(acc[a][c], 0.0f);

    inv_load(sb, n0, o0, b, 0, tid);

    const int NCH = 1024 / 32;
    for (int c = 0; c < NCH; c++) {
        int buf = c & 1;
        if (c + 1 < NCH) {
            inv_load(sb + (buf ^ 1) * STAGE_INV, n0, o0, b, (c + 1) * 32, tid);
            CP_WAIT1();
        } else {
            CP_WAIT0();
        }
        __syncthreads();

        const char* base = sm + buf * STAGE_INV;
        const __nv_bfloat16* Ah = (const __nv_bfloat16*)(base);
        const __nv_bfloat16* Al = (const __nv_bfloat16*)(base + 10240);
        const __nv_bfloat16* Bh = (const __nv_bfloat16*)(base + 20480);
        const __nv_bfloat16* Bl = (const __nv_bfloat16*)(base + 29184);

        #pragma unroll
        for (int ks = 0; ks < 2; ks++) {
            const int kk = ks * 16;
            FragB gh[2], gl[2];
            #pragma unroll
            for (int is_ = 0; is_ < 2; is_++) {
                wmma::load_matrix_sync(gh[is_], Bh + kk * 136 + wi * 32 + is_ * 16, 136);
                wmma::load_matrix_sync(gl[is_], Bl + kk * 136 + wi * 32 + is_ * 16, 136);
            }
            #pragma unroll
            for (int ms = 0; ms < 2; ms++) {
                const int ao = (wm * 32 + ms * 16) * 40 + kk;
                FragA ah, al;
                wmma::load_matrix_sync(ah, Ah + ao, 40);
                wmma::load_matrix_sync(al, Al + ao, 40);
                #pragma unroll
                for (int is_ = 0; is_ < 2; is_++) {
                    wmma::mma_sync(acc[ms][is_], ah, gh[is_], acc[ms][is_]);
                    wmma::mma_sync(acc[ms][is_], ah, gl[is_], acc[ms][is_]);
                    wmma::mma_sync(acc[ms][is_], al, gh[is_], acc[ms][is_]);
                }
            }
        }
        __syncthreads();
    }

    float* bounce = (float*)sm;
    #pragma unroll
    for (int ms = 0; ms < 2; ms++)
        #pragma unroll
        for (int is_ = 0; is_ < 2; is_++)
            wmma::store_matrix_sync(bounce + (wm * 32 + ms * 16) * 136 + wi * 32 + is_ * 16,
                                    acc[ms][is_], 136, wmma::mem_row_major);
    __syncthreads();
    #pragma unroll
    for (int j = 0; j < 8; j++) {
        int idx4 = tid + 512 * j;
        int row = idx4 >> 5, c4 = idx4 & 31;
        float4 bv = *(const float4*)(bounce + row * 136 + c4 * 4);
        size_t a = ((size_t)b * Nn + n0 + row) * Cc + o0 + c4 * 4;
        float4 vv = *(const float4*)(v + a);
        *(float4*)(out + a) = make_float4(vv.x + bv.x, vv.y + bv.y,
                                          vv.z + bv.z, vv.w + bv.w);
    }
}

// ---------------------------------------------------------------------------
extern "C" void kernel_launch(void* const* d_in, const int* in_sizes, int n_in,
                              void* d_out, int out_size) {
    const float* v = (const float*)d_in[0];
    const float* R = (const float*)d_in[1];
    float* out = (float*)d_out;

    const int smF = 2 * STAGE_FWD;
    const int smI = 2 * STAGE_INV;
    cudaFuncSetAttribute(fwd_gemm, cudaFuncAttributeMaxDynamicSharedMemorySize, smF);
    cudaFuncSetAttribute(inv_gemm, cudaFuncAttributeMaxDynamicSharedMemorySize, smI);

    genA_fwd<<<(Mm * Nn) / 256, 256>>>();
    genA_inv<<<(Nn * 2 * Mm) / 256, 256>>>();
    packV<<<(int)(((size_t)Bb * Nn * Cc / 4) / 256), 256>>>(v);
    fwd_gemm<<<dim3(2, 4, 32), 512, smF>>>();
    mid_kernel<<<dim3(Cc / 64, Mm), 256>>>(R);
    pack_G<<<(int)(((size_t)Bb * 2 * Mm * Cc / 4) / 256), 256>>>();
    inv_gemm<<<dim3(2, 32, 32), 512, smI>>>(v, out);
}